// round 6
// baseline (speedup 1.0000x reference)
#include <cuda_runtime.h>
#include <cstdint>

// PadVariable reflect-pad gather — persistent single-wave grid-stride version.
// out[n,t,:] = x[n, reflect(t - pad0[n], lens[n]), :], zero where t >= L+p0+p1.
// Work unit = tile of TILE_T t's for one n. 256 threads: f4 = tid & 15,
// trow = tid >> 4, UNROLL=4 t's/thread. Grid = 1216 persistent blocks
// (8/SM x 152 SMs on GB300) striding over all tiles -> one wave.

#define F4_      16   // F=64 floats -> 16 float4
#define TROWS_   16   // 256 / F4_
#define UNROLL_  4
#define TILE_T_  (TROWS_ * UNROLL_)   // 64 t per tile
#define PERSISTENT_BLOCKS 1216        // 8 blocks/SM * 152 SMs (GB300)

__global__ __launch_bounds__(256)
void pad_variable_kernel(const float4* __restrict__ x4,
                         const int* __restrict__ lens,
                         const int* __restrict__ pad,  // (2, N)
                         float4* __restrict__ out4,
                         int N, int T, int Tp,
                         int tiles_per_row, int total_tiles) {
    const int tid  = threadIdx.x;
    const int f4   = tid & (F4_ - 1);
    const int trow = tid >> 4;

    for (int tile = blockIdx.x; tile < total_tiles; tile += gridDim.x) {
        const int n  = tile / tiles_per_row;
        const int tt = tile - n * tiles_per_row;
        const int t0 = tt * TILE_T_ + trow;

        const int L  = __ldg(&lens[n]);
        const int p0 = __ldg(&pad[n]);
        const int p1 = __ldg(&pad[N + n]);
        const int vlim = L + p0 + p1;

        // 32-bit element offsets (max ~6.3M float4 < 2^31) — safe here.
        const float4* __restrict__ xrow = x4 + (unsigned)(n * T * F4_);
        float4* __restrict__ orow       = out4 + (unsigned)(n * Tp * F4_);

        int t[UNROLL_];
        int idx[UNROLL_];
        bool store_ok[UNROLL_];
        bool load_ok[UNROLL_];

        #pragma unroll
        for (int u = 0; u < UNROLL_; u++) {
            t[u] = t0 + u * TROWS_;
            store_ok[u] = t[u] < Tp;
            int rel = t[u] - p0;
            int s = (rel < 0) ? -rel : ((rel < L) ? rel : (2 * L - rel - 2));
            s = min(max(s, 0), T - 1);
            idx[u] = s * F4_ + f4;
            load_ok[u] = store_ok[u] && (t[u] < vlim);
        }

        // Front-batched independent loads (MLP = 4).
        float4 v[UNROLL_];
        #pragma unroll
        for (int u = 0; u < UNROLL_; u++) {
            if (load_ok[u])
                v[u] = __ldg(&xrow[(unsigned)idx[u]]);
            else
                v[u] = make_float4(0.f, 0.f, 0.f, 0.f);
        }

        #pragma unroll
        for (int u = 0; u < UNROLL_; u++) {
            if (store_ok[u])
                orow[(unsigned)(t[u] * F4_ + f4)] = v[u];
        }
    }
}

extern "C" void kernel_launch(void* const* d_in, const int* in_sizes, int n_in,
                              void* d_out, int out_size) {
    const float* x    = (const float*)d_in[0];  // (N, T, F) float32
    const int*   lens = (const int*)d_in[1];    // (N,)
    const int*   pad  = (const int*)d_in[2];    // (2, N)

    float* out = (float*)d_out;

    const int N = in_sizes[1];           // 64
    const int F = 64;                    // feature dim (16 float4)
    const int T = in_sizes[0] / (N * F); // 4096
    const int Tp = out_size / (N * F);

    const int tiles_per_row = (Tp + TILE_T_ - 1) / TILE_T_;
    const int total_tiles = tiles_per_row * N;
    const int blocks = total_tiles < PERSISTENT_BLOCKS ? total_tiles
                                                       : PERSISTENT_BLOCKS;

    pad_variable_kernel<<<blocks, 256>>>(
        (const float4*)x, lens, pad, (float4*)out,
        N, T, Tp, tiles_per_row, total_tiles);
}

// round 7
// speedup vs baseline: 1.0943x; 1.0943x over previous
#include <cuda_runtime.h>
#include <cstdint>

// PadVariable reflect-pad gather with SMEM-staged bulk stores.
// out[n,t,:] = x[n, reflect(t - pad0[n], lens[n]), :], zero where t >= L+p0+p1.
// Per block: gather TILE_T=64 t's (one n) into a 16KB smem tile, then issue a
// single cp.async.bulk (SMEM -> GMEM) for the whole contiguous output tile.
// This replaces 2048 STG.128 per block with one bulk copy (no L1 store pass,
// no per-STG issue cost).

#define F4_      16   // F=64 floats -> 16 float4
#define TROWS_   16   // 256 / F4_
#define UNROLL_  4
#define TILE_T_  (TROWS_ * UNROLL_)   // 64 t per tile
#define ROW_BYTES_ 256                // F * 4 bytes per t

__global__ __launch_bounds__(256)
void pad_variable_kernel(const float4* __restrict__ x4,
                         const int* __restrict__ lens,
                         const int* __restrict__ pad,  // (2, N)
                         float4* __restrict__ out4,
                         int N, int T, int Tp) {
    __shared__ __align__(128) float4 buf[TILE_T_ * F4_];  // 16 KB

    const int n    = blockIdx.y;
    const int tid  = threadIdx.x;
    const int f4   = tid & (F4_ - 1);
    const int trow = tid >> 4;
    const int tbase = blockIdx.x * TILE_T_;
    const int t0   = tbase + trow;

    const int L  = __ldg(&lens[n]);
    const int p0 = __ldg(&pad[n]);
    const int p1 = __ldg(&pad[N + n]);
    const int vlim = L + p0 + p1;

    // 32-bit element offsets (max ~6.3M float4 < 2^31) — safe here.
    const float4* __restrict__ xrow = x4 + (unsigned)(n * T * F4_);

    int t[UNROLL_];
    int idx[UNROLL_];
    bool row_ok[UNROLL_];
    bool load_ok[UNROLL_];

    #pragma unroll
    for (int u = 0; u < UNROLL_; u++) {
        t[u] = t0 + u * TROWS_;
        row_ok[u] = t[u] < Tp;
        int rel = t[u] - p0;
        int s = (rel < 0) ? -rel : ((rel < L) ? rel : (2 * L - rel - 2));
        s = min(max(s, 0), T - 1);
        idx[u] = s * F4_ + f4;
        load_ok[u] = row_ok[u] && (t[u] < vlim);
    }

    // Front-batched independent loads (MLP = 4).
    float4 v[UNROLL_];
    #pragma unroll
    for (int u = 0; u < UNROLL_; u++) {
        if (load_ok[u])
            v[u] = __ldg(&xrow[(unsigned)idx[u]]);
        else
            v[u] = make_float4(0.f, 0.f, 0.f, 0.f);
    }

    // Stage into SMEM (t-major, 256B rows — conflict-free: consecutive
    // threads hit consecutive 16B).
    #pragma unroll
    for (int u = 0; u < UNROLL_; u++) {
        if (row_ok[u])
            buf[(trow + u * TROWS_) * F4_ + f4] = v[u];
    }
    __syncthreads();

    // One bulk store for the whole contiguous output tile.
    if (tid == 0) {
        int rows = Tp - tbase;
        if (rows > TILE_T_) rows = TILE_T_;
        const unsigned bytes = (unsigned)rows * ROW_BYTES_;
        float4* gdst = out4 + (unsigned)((n * Tp + tbase) * F4_);

        uint32_t saddr;
        asm("{ .reg .u64 tmp; cvta.to.shared.u64 tmp, %1; cvt.u32.u64 %0, tmp; }"
            : "=r"(saddr) : "l"(buf));

        asm volatile("fence.proxy.async.shared::cta;" ::: "memory");
        asm volatile(
            "cp.async.bulk.global.shared::cta.bulk_group [%0], [%1], %2;"
            :: "l"(gdst), "r"(saddr), "r"(bytes) : "memory");
        asm volatile("cp.async.bulk.commit_group;" ::: "memory");
        asm volatile("cp.async.bulk.wait_group 0;" ::: "memory");
    }
}

extern "C" void kernel_launch(void* const* d_in, const int* in_sizes, int n_in,
                              void* d_out, int out_size) {
    const float* x    = (const float*)d_in[0];  // (N, T, F) float32
    const int*   lens = (const int*)d_in[1];    // (N,)
    const int*   pad  = (const int*)d_in[2];    // (2, N)

    float* out = (float*)d_out;

    const int N = in_sizes[1];           // 64
    const int F = 64;                    // feature dim (16 float4)
    const int T = in_sizes[0] / (N * F); // 4096
    const int Tp = out_size / (N * F);

    dim3 grid((Tp + TILE_T_ - 1) / TILE_T_, N);
    pad_variable_kernel<<<grid, 256>>>(
        (const float4*)x, lens, pad, (float4*)out, N, T, Tp);
}